// round 10
// baseline (speedup 1.0000x reference)
#include <cuda_runtime.h>

#define N_HID     128
#define N_ETYPES  10
#define N_EDGES   100000
#define TOTAL_EDGES (N_ETYPES * N_EDGES)
#define EPW       16   // edges per warp

// One warp per 16 consecutive edges; 4 quarters of 8 batched gathers.
// Per-quarter partial reduction (shfl16+mux) collapses 4 accs -> 2 while the
// NEXT quarter's gathers are in flight, hiding 16/31 SHFLs under load stalls
// and cutting live regs so 9 blocks/SM fit (36 warps, 56% occ).
__global__ void __launch_bounds__(128, 9) distmult_kernel(
    const float* __restrict__ h,
    const float* __restrict__ W,
    const int* __restrict__ src,
    const int* __restrict__ dst,
    const int* __restrict__ rel,
    float* __restrict__ out)
{
    const int warp = (blockIdx.x * blockDim.x + threadIdx.x) >> 5;
    const int lane = threadIdx.x & 31;
    const int e0 = warp * EPW;
    if (e0 >= TOTAL_EDGES) return;

    const int t = e0 / N_EDGES;            // 100000 % 16 == 0: no straddle
    const int r = __ldg(&rel[t]);
    const float4 w = __ldg((const float4*)(W + r * N_HID) + lane);

    const bool h4 = lane & 16;
    float rv[8];   // 2 partials per quarter; rv[2q+j] holds edge 4q + 2*h4 + j

#define QUARTER(qi)                                                          \
    {                                                                        \
        const int4 s4 = __ldg((const int4*)(src + e0 + 4 * (qi)));           \
        const int4 d4 = __ldg((const int4*)(dst + e0 + 4 * (qi)));           \
        float4 a0 = __ldg((const float4*)(h + (size_t)s4.x * N_HID) + lane); \
        float4 a1 = __ldg((const float4*)(h + (size_t)s4.y * N_HID) + lane); \
        float4 a2 = __ldg((const float4*)(h + (size_t)s4.z * N_HID) + lane); \
        float4 a3 = __ldg((const float4*)(h + (size_t)s4.w * N_HID) + lane); \
        float4 b0 = __ldg((const float4*)(h + (size_t)d4.x * N_HID) + lane); \
        float4 b1 = __ldg((const float4*)(h + (size_t)d4.y * N_HID) + lane); \
        float4 b2 = __ldg((const float4*)(h + (size_t)d4.z * N_HID) + lane); \
        float4 b3 = __ldg((const float4*)(h + (size_t)d4.w * N_HID) + lane); \
        float t0 = a0.x * w.x * b0.x;                                        \
        t0 = fmaf(a0.y * w.y, b0.y, t0);                                     \
        t0 = fmaf(a0.z * w.z, b0.z, t0);                                     \
        t0 = fmaf(a0.w * w.w, b0.w, t0);                                     \
        float t1 = a1.x * w.x * b1.x;                                        \
        t1 = fmaf(a1.y * w.y, b1.y, t1);                                     \
        t1 = fmaf(a1.z * w.z, b1.z, t1);                                     \
        t1 = fmaf(a1.w * w.w, b1.w, t1);                                     \
        float t2 = a2.x * w.x * b2.x;                                        \
        t2 = fmaf(a2.y * w.y, b2.y, t2);                                     \
        t2 = fmaf(a2.z * w.z, b2.z, t2);                                     \
        t2 = fmaf(a2.w * w.w, b2.w, t2);                                     \
        float t3 = a3.x * w.x * b3.x;                                        \
        t3 = fmaf(a3.y * w.y, b3.y, t3);                                     \
        t3 = fmaf(a3.z * w.z, b3.z, t3);                                     \
        t3 = fmaf(a3.w * w.w, b3.w, t3);                                     \
        t0 += __shfl_xor_sync(0xffffffffu, t0, 16);                          \
        t1 += __shfl_xor_sync(0xffffffffu, t1, 16);                          \
        t2 += __shfl_xor_sync(0xffffffffu, t2, 16);                          \
        t3 += __shfl_xor_sync(0xffffffffu, t3, 16);                          \
        rv[2 * (qi) + 0] = h4 ? t2 : t0;                                     \
        rv[2 * (qi) + 1] = h4 ? t3 : t1;                                     \
    }

    QUARTER(0)
    QUARTER(1)
    QUARTER(2)
    QUARTER(3)
#undef QUARTER

    // Stage B: shfl8 on 8 values, mux on bit3 -> w[q] = edge 4q + 2*b4 + b3
    #pragma unroll
    for (int k = 0; k < 8; k++)
        rv[k] += __shfl_xor_sync(0xffffffffu, rv[k], 8);
    const bool h3 = lane & 8;
    float wv[4];
    #pragma unroll
    for (int q = 0; q < 4; q++)
        wv[q] = h3 ? rv[2 * q + 1] : rv[2 * q];

    // Stage C: shfl4, mux on bit2 -> u[n] = edge 4*(2n+b2) + 2*b4 + b3
    #pragma unroll
    for (int k = 0; k < 4; k++)
        wv[k] += __shfl_xor_sync(0xffffffffu, wv[k], 4);
    const bool h2 = lane & 4;
    float u0 = h2 ? wv[1] : wv[0];
    float u1 = h2 ? wv[3] : wv[2];

    // Stage D: shfl2, mux on bit1 -> s = edge 8*b1 + 4*b2 + 2*b4 + b3
    u0 += __shfl_xor_sync(0xffffffffu, u0, 2);
    u1 += __shfl_xor_sync(0xffffffffu, u1, 2);
    float s = (lane & 2) ? u1 : u0;

    // Stage E: shfl1 -> fully reduced; lane pair {b0} holds one edge
    s += __shfl_xor_sync(0xffffffffu, s, 1);

    const float sig = 1.0f / (1.0f + __expf(-s));
    if ((lane & 1) == 0) {
        const int eid = ((lane >> 1) & 1) * 8 + ((lane >> 2) & 1) * 4
                      + ((lane >> 4) & 1) * 2 + ((lane >> 3) & 1);
        out[e0 + eid] = sig;   // 16 floats within one 64B line
    }
}

extern "C" void kernel_launch(void* const* d_in, const int* in_sizes, int n_in,
                              void* d_out, int out_size)
{
    const float* h   = (const float*)d_in[0];   // [N_NODES, 128]
    const float* W   = (const float*)d_in[1];   // [10, 128]
    const int*   src = (const int*)d_in[2];     // [10, 100000] int32
    const int*   dst = (const int*)d_in[3];     // [10, 100000] int32
    const int*   rel = (const int*)d_in[4];     // [10] int32
    float* out = (float*)d_out;                 // [10, 100000]

    const int threads = 128;                     // 4 warps/block, 64 edges/block
    const int warps_needed = TOTAL_EDGES / EPW;  // 62500
    const int blocks = (warps_needed * 32 + threads - 1) / threads;  // 15625
    distmult_kernel<<<blocks, threads>>>(h, W, src, dst, rel, out);
}

// round 11
// speedup vs baseline: 1.1132x; 1.1132x over previous
#include <cuda_runtime.h>

#define N_HID     128
#define N_ETYPES  10
#define N_EDGES   100000
#define TOTAL_EDGES (N_ETYPES * N_EDGES)
#define EPW       8   // edges per warp (2 groups of 4)

// Octet layout: 8 lanes per edge. o = lane>>3 selects the edge within a group
// of 4; j = lane&7 selects a 16B slice of each 128B chunk (4 chunks per row).
// Each lane accumulates its edge's partial dot in ONE register across chunks,
// so a warp needs only 2 accumulators for 8 edges and the reduction is
// 4 SHFL + 1 mux total. Per load instruction: 4 rows x 128B = 4 full lines.
__global__ void __launch_bounds__(128, 9) distmult_kernel(
    const float* __restrict__ h,
    const float* __restrict__ W,
    const int* __restrict__ src,
    const int* __restrict__ dst,
    const int* __restrict__ rel,
    float* __restrict__ out)
{
    const int warp = (blockIdx.x * blockDim.x + threadIdx.x) >> 5;
    const int lane = threadIdx.x & 31;
    const int e0 = warp * EPW;
    if (e0 >= TOTAL_EDGES) return;

    const int j = lane & 7;        // 16B slice within chunk
    const int o = lane >> 3;       // edge within group

    const int t = e0 / N_EDGES;    // 100000 % 8 == 0: no etype straddle
    const int r = __ldg(&rel[t]);
    const float* wrow = W + r * N_HID;

    float acc0, acc1;

#define GROUP(accv, gbase)                                                     \
    {                                                                          \
        const int s = __ldg(src + (gbase) + o);                                \
        const int d = __ldg(dst + (gbase) + o);                                \
        const float* sa = h + (size_t)s * N_HID;                               \
        const float* sb = h + (size_t)d * N_HID;                               \
        /* 8 independent gathers: 4 chunks x {src,dst} */                      \
        const float4 a0 = __ldg((const float4*)(sa +  0) + j);                 \
        const float4 a1 = __ldg((const float4*)(sa + 32) + j);                 \
        const float4 a2 = __ldg((const float4*)(sa + 64) + j);                 \
        const float4 a3 = __ldg((const float4*)(sa + 96) + j);                 \
        const float4 b0 = __ldg((const float4*)(sb +  0) + j);                 \
        const float4 b1 = __ldg((const float4*)(sb + 32) + j);                 \
        const float4 b2 = __ldg((const float4*)(sb + 64) + j);                 \
        const float4 b3 = __ldg((const float4*)(sb + 96) + j);                 \
        const float4 w0 = __ldg((const float4*)(wrow +  0) + j);               \
        const float4 w1 = __ldg((const float4*)(wrow + 32) + j);               \
        const float4 w2 = __ldg((const float4*)(wrow + 64) + j);               \
        const float4 w3 = __ldg((const float4*)(wrow + 96) + j);               \
        float x = a0.x * w0.x * b0.x;                                          \
        x = fmaf(a0.y * w0.y, b0.y, x);                                        \
        x = fmaf(a0.z * w0.z, b0.z, x);                                        \
        x = fmaf(a0.w * w0.w, b0.w, x);                                        \
        x = fmaf(a1.x * w1.x, b1.x, x);                                        \
        x = fmaf(a1.y * w1.y, b1.y, x);                                        \
        x = fmaf(a1.z * w1.z, b1.z, x);                                        \
        x = fmaf(a1.w * w1.w, b1.w, x);                                        \
        x = fmaf(a2.x * w2.x, b2.x, x);                                        \
        x = fmaf(a2.y * w2.y, b2.y, x);                                        \
        x = fmaf(a2.z * w2.z, b2.z, x);                                        \
        x = fmaf(a2.w * w2.w, b2.w, x);                                        \
        x = fmaf(a3.x * w3.x, b3.x, x);                                        \
        x = fmaf(a3.y * w3.y, b3.y, x);                                        \
        x = fmaf(a3.z * w3.z, b3.z, x);                                        \
        accv = fmaf(a3.w * w3.w, b3.w, x);                                     \
    }

    GROUP(acc0, e0)        // edges e0   .. e0+3  (octet o -> edge e0+o)
    GROUP(acc1, e0 + 4)    // edges e0+4 .. e0+7
#undef GROUP

    // Reduce within octet (8 lanes) for both groups: 4 SHFL + 1 mux.
    acc0 += __shfl_xor_sync(0xffffffffu, acc0, 4);
    acc1 += __shfl_xor_sync(0xffffffffu, acc1, 4);
    float m = (lane & 4) ? acc1 : acc0;    // bit2 selects group
    m += __shfl_xor_sync(0xffffffffu, m, 2);
    m += __shfl_xor_sync(0xffffffffu, m, 1);
    // lane l: octet o = l>>3 , group g = (l>>2)&1 -> edge e0 + 4g + o

    const float sig = 1.0f / (1.0f + __expf(-m));
    if ((lane & 3) == 0) {
        const int g = (lane >> 2) & 1;
        out[e0 + 4 * g + o] = sig;   // 8 floats within one 32B span
    }
}

extern "C" void kernel_launch(void* const* d_in, const int* in_sizes, int n_in,
                              void* d_out, int out_size)
{
    const float* h   = (const float*)d_in[0];   // [N_NODES, 128]
    const float* W   = (const float*)d_in[1];   // [10, 128]
    const int*   src = (const int*)d_in[2];     // [10, 100000] int32
    const int*   dst = (const int*)d_in[3];     // [10, 100000] int32
    const int*   rel = (const int*)d_in[4];     // [10] int32
    float* out = (float*)d_out;                 // [10, 100000]

    const int threads = 128;                     // 4 warps/block, 32 edges/block
    const int warps_needed = TOTAL_EDGES / EPW;  // 125000
    const int blocks = (warps_needed * 32 + threads - 1) / threads;  // 31250
    distmult_kernel<<<blocks, threads>>>(h, W, src, dst, rel, out);
}